// round 13
// baseline (speedup 1.0000x reference)
#include <cuda_runtime.h>
#include <cuda_bf16.h>

#define CROP 81
#define PIX  (CROP * CROP)        // 6561
#define SPLIT 3                   // 27 rows per block
#define THREADS 256               // 243 productive (3 groups x 81 cols)

// One block = one (n,p) crop, 27 output rows. Each thread owns a fixed
// column j and 9 consecutive rows (3 chunks of 3, boundary hl carried in
// registers: 10 image rows per 9 outputs). The right bilinear tap comes from
// the right-neighbor lane via warp shuffle (x-step is exactly 1 pixel), with
// a predicated direct load as fallback at lane 31 / crop borders / clamps.
__global__ __launch_bounds__(THREADS)
void selectnet_kernel(const float* __restrict__ img,
                      const int*   __restrict__ label,
                      const float* __restrict__ points,
                      float*       __restrict__ out,
                      int N)
{
    const int W = 512, H = 512;
    const size_t plane = (size_t)H * W;

    // x: (wx0, wx1, bits[c0 | c1<<9 | (lx+1)<<18], 0)
    // y: (wy0, wy1, bits[y0 raw unclamped], bits[lyrow or -1])
    __shared__ float4 sxt[CROP];
    __shared__ float4 syt[CROP];

    const int q = blockIdx.x;       // n*6 + p
    const int p = q % 6;
    const int n = q / 6;
    const int t = threadIdx.x;

    if (t < CROP) {
        // ---- exact replication of reference float32 op chain ----
        const float* pt = points + (size_t)n * 18;
        float py, px;
        if (p < 5) {
            py = pt[(p + 1) * 2 + 0];
            px = pt[(p + 1) * 2 + 1];
        } else {
            py = __fdiv_rn(__fadd_rn(__fadd_rn(pt[12], pt[14]), pt[16]), 3.0f);
            px = __fdiv_rn(__fadd_rn(__fadd_rn(pt[13], pt[15]), pt[17]), 3.0f);
        }
        const float fw = 511.0f, fh = 511.0f;
        const float sx = (float)(80.0 / 511.0);   // (CROP-1)/(W-1)
        const float sy = (float)(80.0 / 512.0);   // (CROP-1)/H  (reference asymmetry)
        const float delta = __fdiv_rn(2.0f, 80.0f);

        float tx = __fadd_rn(-1.0f, __fdiv_rn(__fmul_rn(2.0f, px), fw));
        float ty = __fadd_rn(-1.0f, __fdiv_rn(__fmul_rn(2.0f, py), fh));
        float base = __fadd_rn(-1.0f, __fmul_rn((float)t, delta));
        float gx = __fadd_rn(__fmul_rn(sx, base), tx);
        float gy = __fadd_rn(__fmul_rn(sy, base), ty);
        float ix = __fmul_rn(__fmul_rn(__fadd_rn(gx, 1.0f), 0.5f), fw);
        float iy = __fmul_rn(__fmul_rn(__fadd_rn(gy, 1.0f), 0.5f), fh);

        // x table (index = j)
        float x0f = floorf(ix);
        float wx1v = ix - x0f;
        int x0 = (int)x0f, x1 = x0 + 1;
        float wx0 = (x0 >= 0 && x0 <= W - 1) ? (1.0f - wx1v) : 0.0f;
        float wx1 = (x1 >= 0 && x1 <= W - 1) ? wx1v : 0.0f;
        int c0 = min(max(x0, 0), W - 1);
        int c1 = min(max(x1, 0), W - 1);
        float xr = rintf(ix);
        int lx = (xr >= 0.0f && xr <= fw) ? (int)xr : -1;
        sxt[t] = make_float4(wx0, wx1,
                             __int_as_float(c0 | (c1 << 9) | ((lx + 1) << 18)), 0.0f);

        // y table (index = i): keep y0 UNCLAMPED (row base for tap reuse)
        float y0f = floorf(iy);
        float wy1v = iy - y0f;
        int y0 = (int)y0f, y1 = y0 + 1;
        float wy0 = (y0 >= 0 && y0 <= H - 1) ? (1.0f - wy1v) : 0.0f;
        float wy1 = (y1 >= 0 && y1 <= H - 1) ? wy1v : 0.0f;
        float yr = rintf(iy);
        int lyrow = (yr >= 0.0f && yr <= fh) ? ((int)yr) * W : -1;
        syt[t] = make_float4(wy0, wy1, __int_as_float(y0), __int_as_float(lyrow));
    }
    __syncthreads();

    // NOTE: no early return — all 256 threads stay for convergent shuffles.
    const bool active = (t < 3 * CROP);
    int g = t / CROP;                  // 0..3
    int j = t - g * CROP;
    if (!active) { g = 2; j = 80; }    // tail lanes duplicate (g=2, j=80)
    const int i0 = blockIdx.y * 27 + g * 9;
    const int lane = t & 31;

    float4 xt = sxt[j];
    int xp = __float_as_int(xt.z);
    const int c0 = xp & 511, c1 = (xp >> 9) & 511, lx = (xp >> 18) - 1;

    // shuffle-sharing feasibility flag (constant per thread):
    // right neighbor's c0 tap must be exactly this thread's c1 tap.
    int c0n = __shfl_down_sync(0xffffffffu, c0, 1);
    const bool okx = (lane != 31) && (c0n == c1);

    // pair-load: a = img tap at c0; b = tap at c1 (shfl from neighbor, or
    // predicated direct load issued independently alongside a).
    auto ld2 = [&](const float* rowp, float& a, float& b) {
        a = __ldg(rowp + c0);
        float bf = 0.0f;
        if (!okx) bf = __ldg(rowp + c1);
        float bs = __shfl_down_sync(0xffffffffu, a, 1);
        b = okx ? bs : bf;
    };

    const float* imgn = img   + (size_t)n * 3 * plane;
    const int*   labn = label + (size_t)n * plane;
    float*       outq  = out + (size_t)q * 3 * PIX + (size_t)i0 * CROP + j;
    float*       predq = out + (size_t)N * 6 * 3 * PIX + (size_t)q * PIX + (size_t)i0 * CROP + j;
    const int target = p + 1;

    const int base0 = __float_as_int(syt[i0].z);   // raw y0 of first row

    float hp2[3], hp1[3];   // per-channel carries: hl[3m-1], hl[3m]

    // ================= chunk 0 (rows k = 0..2, window rows 0..3) =================
    {
        float4 ya = syt[i0], yb = syt[i0 + 1], yc = syt[i0 + 2];
        bool pb = (__float_as_int(yb.z) - base0) == 1;
        bool pc = (__float_as_int(yc.z) - base0) == 2;
        int lyr0 = __float_as_int(ya.w);
        int lyr1 = __float_as_int(yb.w);
        int lyr2 = __float_as_int(yc.w);

        int ro0 = min(max(base0 + 0, 0), H - 1) << 9;
        int ro1 = min(max(base0 + 1, 0), H - 1) << 9;
        int ro2 = min(max(base0 + 2, 0), H - 1) << 9;
        int ro3 = min(max(base0 + 3, 0), H - 1) << 9;

        int la0 = ((lx | lyr0) >= 0) ? __ldg(labn + lyr0 + lx) : 0;
        int la1 = ((lx | lyr1) >= 0) ? __ldg(labn + lyr1 + lx) : 0;
        int la2 = ((lx | lyr2) >= 0) ? __ldg(labn + lyr2 + lx) : 0;

        #pragma unroll
        for (int c = 0; c < 3; ++c) {
            const float* cp = imgn + (size_t)c * plane;
            float a0, b0, a1, b1, a2, b2, a3, b3;
            ld2(cp + ro0, a0, b0);
            ld2(cp + ro1, a1, b1);
            ld2(cp + ro2, a2, b2);
            ld2(cp + ro3, a3, b3);

            float h0 = a0 * xt.x + b0 * xt.y;
            float h1 = a1 * xt.x + b1 * xt.y;
            float h2 = a2 * xt.x + b2 * xt.y;
            float h3 = a3 * xt.x + b3 * xt.y;

            float o0 = h0 * ya.x + h1 * ya.y;
            float o1 = (pb ? h1 : h0) * yb.x + (pb ? h2 : h1) * yb.y;
            float o2 = (pc ? h2 : h1) * yc.x + (pc ? h3 : h2) * yc.y;

            if (active) {
                float* op = outq + (size_t)c * PIX;
                __stcs(op + 0 * CROP, o0);
                __stcs(op + 1 * CROP, o1);
                __stcs(op + 2 * CROP, o2);
            }
            hp2[c] = h2; hp1[c] = h3;
        }

        float pr0, pr1, pr2;
        if (p < 5) {
            pr0 = (la0 == target) ? 1.0f : 0.0f;
            pr1 = (la1 == target) ? 1.0f : 0.0f;
            pr2 = (la2 == target) ? 1.0f : 0.0f;
        } else {
            pr0 = (la0 == 6) ? 1.0f : (la0 == 7) ? 2.0f : (la0 == 8) ? 3.0f : 0.0f;
            pr1 = (la1 == 6) ? 1.0f : (la1 == 7) ? 2.0f : (la1 == 8) ? 3.0f : 0.0f;
            pr2 = (la2 == 6) ? 1.0f : (la2 == 7) ? 2.0f : (la2 == 8) ? 3.0f : 0.0f;
        }
        if (active) {
            __stcs(predq + 0 * CROP, pr0);
            __stcs(predq + 1 * CROP, pr1);
            __stcs(predq + 2 * CROP, pr2);
        }
    }

    // ========== chunks m = 1,2 (rows 3m..3m+2, new window rows 3m+1..3m+3) =======
    #pragma unroll
    for (int m = 1; m < 3; ++m) {
        const int k0 = 3 * m;
        float4 ya = syt[i0 + k0], yb = syt[i0 + k0 + 1], yc = syt[i0 + k0 + 2];
        bool pa = (__float_as_int(ya.z) - base0) == k0;
        bool pb = (__float_as_int(yb.z) - base0) == k0 + 1;
        bool pc = (__float_as_int(yc.z) - base0) == k0 + 2;
        int lyr0 = __float_as_int(ya.w);
        int lyr1 = __float_as_int(yb.w);
        int lyr2 = __float_as_int(yc.w);

        int roA = min(max(base0 + k0 + 1, 0), H - 1) << 9;
        int roB = min(max(base0 + k0 + 2, 0), H - 1) << 9;
        int roC = min(max(base0 + k0 + 3, 0), H - 1) << 9;

        int la0 = ((lx | lyr0) >= 0) ? __ldg(labn + lyr0 + lx) : 0;
        int la1 = ((lx | lyr1) >= 0) ? __ldg(labn + lyr1 + lx) : 0;
        int la2 = ((lx | lyr2) >= 0) ? __ldg(labn + lyr2 + lx) : 0;

        #pragma unroll
        for (int c = 0; c < 3; ++c) {
            const float* cp = imgn + (size_t)c * plane;
            float aA, bA, aB, bB, aC, bC;
            ld2(cp + roA, aA, bA);
            ld2(cp + roB, aB, bB);
            ld2(cp + roC, aC, bC);

            float h1 = aA * xt.x + bA * xt.y;   // hl[k0+1]
            float h2 = aB * xt.x + bB * xt.y;   // hl[k0+2]
            float h3 = aC * xt.x + bC * xt.y;   // hl[k0+3]
            float hm1 = hp1[c];                 // hl[k0]
            float hm2 = hp2[c];                 // hl[k0-1]

            float o0 = (pa ? hm1 : hm2) * ya.x + (pa ? h1 : hm1) * ya.y;
            float o1 = (pb ? h1 : hm1) * yb.x + (pb ? h2 : h1) * yb.y;
            float o2 = (pc ? h2 : h1) * yc.x + (pc ? h3 : h2) * yc.y;

            if (active) {
                float* op = outq + (size_t)c * PIX + (size_t)k0 * CROP;
                __stcs(op + 0 * CROP, o0);
                __stcs(op + 1 * CROP, o1);
                __stcs(op + 2 * CROP, o2);
            }
            hp2[c] = h2; hp1[c] = h3;
        }

        float pr0, pr1, pr2;
        if (p < 5) {
            pr0 = (la0 == target) ? 1.0f : 0.0f;
            pr1 = (la1 == target) ? 1.0f : 0.0f;
            pr2 = (la2 == target) ? 1.0f : 0.0f;
        } else {
            pr0 = (la0 == 6) ? 1.0f : (la0 == 7) ? 2.0f : (la0 == 8) ? 3.0f : 0.0f;
            pr1 = (la1 == 6) ? 1.0f : (la1 == 7) ? 2.0f : (la1 == 8) ? 3.0f : 0.0f;
            pr2 = (la2 == 6) ? 1.0f : (la2 == 7) ? 2.0f : (la2 == 8) ? 3.0f : 0.0f;
        }
        if (active) {
            float* pp = predq + (size_t)k0 * CROP;
            __stcs(pp + 0 * CROP, pr0);
            __stcs(pp + 1 * CROP, pr1);
            __stcs(pp + 2 * CROP, pr2);
        }
    }
}

extern "C" void kernel_launch(void* const* d_in, const int* in_sizes, int n_in,
                              void* d_out, int out_size) {
    const float* img    = (const float*)d_in[0];   // (N, 3, 512, 512) f32
    const int*   label  = (const int*)  d_in[1];   // (N, 512, 512) i32
    const float* points = (const float*)d_in[2];   // (N, 9, 2) f32
    float* out = (float*)d_out;

    int N = in_sizes[2] / 18;                      // points = N*9*2

    dim3 grid(N * 6, SPLIT);
    selectnet_kernel<<<grid, THREADS>>>(img, label, points, out, N);
}